// round 1
// baseline (speedup 1.0000x reference)
#include <cuda_runtime.h>
#include <math.h>

#define N_NODES 20000
#define N_EDGES 640000
#define DIM     128
#define NCOL    512   // 4 gates * 128 outputs, interleaved as col = o*4 + g
#define KTOT    512   // concat K: [aggX | X | aggH | H]

// ---------------- scratch (__device__ globals; no allocation allowed) ----------------
__device__ int   g_cnt[N_NODES];
__device__ int   g_off[N_NODES + 1];
__device__ int   g_pos[N_NODES];
__device__ int   g_srcp[N_EDGES];
__device__ float g_wp[N_EDGES];
__device__ float g_aggX[N_NODES * DIM];
__device__ float g_aggH[N_NODES * DIM];
__device__ float g_B[KTOT * NCOL];

// ---------------- CSR build ----------------
__global__ void zero_cnt_kernel() {
    int i = blockIdx.x * blockDim.x + threadIdx.x;
    if (i < N_NODES) g_cnt[i] = 0;
}

__global__ void count_kernel(const int* __restrict__ ei) {
    int e = blockIdx.x * blockDim.x + threadIdx.x;
    if (e < N_EDGES) atomicAdd(&g_cnt[ei[N_EDGES + e]], 1);
}

__global__ void scan_kernel() {
    __shared__ int sh[1024];
    __shared__ int s_carry;
    int t = threadIdx.x;
    if (t == 0) s_carry = 0;
    __syncthreads();
    for (int base = 0; base < N_NODES; base += 1024) {
        int i = base + t;
        int v = (i < N_NODES) ? g_cnt[i] : 0;
        sh[t] = v;
        __syncthreads();
        for (int off = 1; off < 1024; off <<= 1) {
            int x = (t >= off) ? sh[t - off] : 0;
            __syncthreads();
            sh[t] += x;
            __syncthreads();
        }
        int excl = s_carry + sh[t] - v;
        if (i < N_NODES) { g_off[i] = excl; g_pos[i] = excl; }
        __syncthreads();
        if (t == 1023) s_carry += sh[1023];
        __syncthreads();
    }
    if (t == 0) g_off[N_NODES] = s_carry;
}

__global__ void scatter_kernel(const int* __restrict__ ei, const float* __restrict__ ew) {
    int e = blockIdx.x * blockDim.x + threadIdx.x;
    if (e < N_EDGES) {
        int d = ei[N_EDGES + e];
        int p = atomicAdd(&g_pos[d], 1);
        g_srcp[p] = ei[e];
        g_wp[p]   = ew[e];
    }
}

// ---------------- pack concatenated weights: B[k][o*4+g] ----------------
__global__ void pack_weights_kernel(const float* __restrict__ Wx_l,
                                    const float* __restrict__ Wx_r,
                                    const float* __restrict__ Wh_l,
                                    const float* __restrict__ Wh_r) {
    int idx = blockIdx.x * blockDim.x + threadIdx.x;
    if (idx >= KTOT * NCOL) return;
    int k = idx >> 9;        // 0..511
    int n = idx & 511;
    int o = n >> 2, g = n & 3;
    int kb = k >> 7, d = k & 127;
    const float* W = (kb == 0) ? Wx_l : (kb == 1) ? Wx_r : (kb == 2) ? Wh_l : Wh_r;
    g_B[idx] = W[(g * DIM + d) * DIM + o];
}

// ---------------- aggregation: 1 warp per node ----------------
__global__ void aggregate_kernel(const float* __restrict__ X, const float* __restrict__ H) {
    int warp = (blockIdx.x * blockDim.x + threadIdx.x) >> 5;
    int lane = threadIdx.x & 31;
    if (warp >= N_NODES) return;
    int beg = g_off[warp], end = g_off[warp + 1];
    float4 ax = make_float4(0.f, 0.f, 0.f, 0.f);
    float4 ah = make_float4(0.f, 0.f, 0.f, 0.f);
    for (int e = beg; e < end; e++) {
        int   s = g_srcp[e];
        float w = g_wp[e];
        float4 xv = __ldg((const float4*)(X + (size_t)s * DIM) + lane);
        float4 hv = __ldg((const float4*)(H + (size_t)s * DIM) + lane);
        ax.x = fmaf(w, xv.x, ax.x); ax.y = fmaf(w, xv.y, ax.y);
        ax.z = fmaf(w, xv.z, ax.z); ax.w = fmaf(w, xv.w, ax.w);
        ah.x = fmaf(w, hv.x, ah.x); ah.y = fmaf(w, hv.y, ah.y);
        ah.z = fmaf(w, hv.z, ah.z); ah.w = fmaf(w, hv.w, ah.w);
    }
    float inv = 1.0f / fmaxf((float)(end - beg), 1.0f);
    ax.x *= inv; ax.y *= inv; ax.z *= inv; ax.w *= inv;
    ah.x *= inv; ah.y *= inv; ah.z *= inv; ah.w *= inv;
    ((float4*)(g_aggX + (size_t)warp * DIM))[lane] = ax;
    ((float4*)(g_aggH + (size_t)warp * DIM))[lane] = ah;
}

// ---------------- fused SGEMM (M=20000, N=512, K=512) + LSTM epilogue ----------------
// block tile 128x128, K-step 16, 256 threads, 8x8 microtile per thread
__global__ __launch_bounds__(256) void gemm_lstm_kernel(
    const float* __restrict__ X, const float* __restrict__ H, const float* __restrict__ C,
    const float* __restrict__ bx, const float* __restrict__ bh, const float* __restrict__ bg,
    const float* __restrict__ wc,
    float* __restrict__ outH, float* __restrict__ outC)
{
    __shared__ float As[2][16][128];
    __shared__ float Bs[2][16][128];

    int t  = threadIdx.x;
    int tx = t & 15, ty = t >> 4;
    int row0  = blockIdx.y * 128;
    int ncol0 = blockIdx.x * 128;

    // A-tile load mapping: thread loads 2 float4 along k for one row
    int am = t & 127;              // row within tile
    int aj = (t >> 7) * 2;         // float4 slot base (0 or 2) within 16-float segment
    int arow = row0 + am; if (arow >= N_NODES) arow = N_NODES - 1;

    // B-tile load mapping
    int bk = t >> 4;               // 0..15 (k row)
    int bn = (t & 15) * 4;         // col base; second float4 at +64

    float acc[8][8];
#pragma unroll
    for (int i = 0; i < 8; i++)
#pragma unroll
        for (int j = 0; j < 8; j++) acc[i][j] = 0.f;

    float4 a0, a1, b0, b1;

    // ---- load tile 0 ----
    {
        const float* pA = g_aggX;  // kt=0 -> k0=0 -> aggX
        const float4* pa = (const float4*)(pA + (size_t)arow * DIM + 0);
        a0 = pa[aj]; a1 = pa[aj + 1];
        const float4* pb = (const float4*)(g_B + (size_t)(0 + bk) * NCOL + ncol0 + bn);
        b0 = pb[0]; b1 = pb[16];
        As[0][aj * 4 + 0][am] = a0.x; As[0][aj * 4 + 1][am] = a0.y;
        As[0][aj * 4 + 2][am] = a0.z; As[0][aj * 4 + 3][am] = a0.w;
        As[0][aj * 4 + 4][am] = a1.x; As[0][aj * 4 + 5][am] = a1.y;
        As[0][aj * 4 + 6][am] = a1.z; As[0][aj * 4 + 7][am] = a1.w;
        *(float4*)&Bs[0][bk][bn]      = b0;
        *(float4*)&Bs[0][bk][bn + 64] = b1;
    }
    __syncthreads();

    int buf = 0;
    for (int kt = 0; kt < 32; kt++) {
        // prefetch next tile into registers
        if (kt < 31) {
            int k0 = (kt + 1) * 16;
            const float* pA = (k0 < 128) ? g_aggX : (k0 < 256) ? X : (k0 < 384) ? g_aggH : H;
            int col = k0 & 127;
            const float4* pa = (const float4*)(pA + (size_t)arow * DIM + col);
            a0 = pa[aj]; a1 = pa[aj + 1];
            const float4* pb = (const float4*)(g_B + (size_t)(k0 + bk) * NCOL + ncol0 + bn);
            b0 = pb[0]; b1 = pb[16];
        }
        // compute on current buffer
#pragma unroll
        for (int k = 0; k < 16; k++) {
            float4 ar0 = *(const float4*)&As[buf][k][ty * 8];
            float4 ar1 = *(const float4*)&As[buf][k][ty * 8 + 4];
            float4 br0 = *(const float4*)&Bs[buf][k][tx * 8];
            float4 br1 = *(const float4*)&Bs[buf][k][tx * 8 + 4];
            float av[8] = {ar0.x, ar0.y, ar0.z, ar0.w, ar1.x, ar1.y, ar1.z, ar1.w};
            float bv[8] = {br0.x, br0.y, br0.z, br0.w, br1.x, br1.y, br1.z, br1.w};
#pragma unroll
            for (int i = 0; i < 8; i++)
#pragma unroll
                for (int j = 0; j < 8; j++)
                    acc[i][j] = fmaf(av[i], bv[j], acc[i][j]);
        }
        if (kt < 31) {
            int nb = buf ^ 1;
            As[nb][aj * 4 + 0][am] = a0.x; As[nb][aj * 4 + 1][am] = a0.y;
            As[nb][aj * 4 + 2][am] = a0.z; As[nb][aj * 4 + 3][am] = a0.w;
            As[nb][aj * 4 + 4][am] = a1.x; As[nb][aj * 4 + 5][am] = a1.y;
            As[nb][aj * 4 + 6][am] = a1.z; As[nb][aj * 4 + 7][am] = a1.w;
            *(float4*)&Bs[nb][bk][bn]      = b0;
            *(float4*)&Bs[nb][bk][bn + 64] = b1;
            __syncthreads();
            buf = nb;
        }
    }

    // ---- LSTM epilogue: this thread holds 8 rows x {2 outputs x 4 gates} ----
    int obase = (ncol0 >> 2) + tx * 2;   // global output-dim index for oo=0
    float bi[2][4], pw[2][3];
#pragma unroll
    for (int oo = 0; oo < 2; oo++) {
        int o = obase + oo;
#pragma unroll
        for (int g = 0; g < 4; g++)
            bi[oo][g] = bx[g * DIM + o] + bh[g * DIM + o] + bg[g * DIM + o];
        pw[oo][0] = wc[0 * DIM + o];
        pw[oo][1] = wc[1 * DIM + o];
        pw[oo][2] = wc[2 * DIM + o];
    }
#pragma unroll
    for (int i = 0; i < 8; i++) {
        int r = row0 + ty * 8 + i;
        if (r >= N_NODES) break;
#pragma unroll
        for (int oo = 0; oo < 2; oo++) {
            int o = obase + oo;
            float cold = C[(size_t)r * DIM + o];
            float gI = acc[i][oo * 4 + 0] + bi[oo][0] + pw[oo][0] * cold;
            float gF = acc[i][oo * 4 + 1] + bi[oo][1] + pw[oo][1] * cold;
            float gT = acc[i][oo * 4 + 2] + bi[oo][2];
            float I = 1.f / (1.f + expf(-gI));
            float F = 1.f / (1.f + expf(-gF));
            float T = tanhf(gT);
            float cnew = fmaf(F, cold, I * T);
            float gO = acc[i][oo * 4 + 3] + bi[oo][3] + pw[oo][2] * cnew;
            float O = 1.f / (1.f + expf(-gO));
            float hnew = O * tanhf(cnew);
            outH[(size_t)r * DIM + o] = hnew;
            outC[(size_t)r * DIM + o] = cnew;
        }
    }
}

// ---------------- launch ----------------
extern "C" void kernel_launch(void* const* d_in, const int* in_sizes, int n_in,
                              void* d_out, int out_size) {
    const float* X    = (const float*)d_in[0];
    const int*   ei   = (const int*)  d_in[1];
    const float* ew   = (const float*)d_in[2];
    const float* H    = (const float*)d_in[3];
    const float* C    = (const float*)d_in[4];
    const float* Wx_l = (const float*)d_in[5];
    const float* Wx_r = (const float*)d_in[6];
    const float* bx   = (const float*)d_in[7];
    const float* Wh_l = (const float*)d_in[8];
    const float* Wh_r = (const float*)d_in[9];
    const float* bh   = (const float*)d_in[10];
    const float* wc   = (const float*)d_in[11];
    const float* bg   = (const float*)d_in[12];

    float* outH = (float*)d_out;
    float* outC = outH + (size_t)N_NODES * DIM;

    zero_cnt_kernel<<<(N_NODES + 255) / 256, 256>>>();
    count_kernel<<<(N_EDGES + 255) / 256, 256>>>(ei);
    scan_kernel<<<1, 1024>>>();
    scatter_kernel<<<(N_EDGES + 255) / 256, 256>>>(ei, ew);
    pack_weights_kernel<<<(KTOT * NCOL + 255) / 256, 256>>>(Wx_l, Wx_r, Wh_l, Wh_r);
    aggregate_kernel<<<(N_NODES * 32 + 255) / 256, 256>>>(X, H);

    dim3 grid(NCOL / 128, (N_NODES + 127) / 128);
    gemm_lstm_kernel<<<grid, 256>>>(X, H, C, bx, bh, bg, wc, outH, outC);
}

// round 3
// speedup vs baseline: 1.5136x; 1.5136x over previous
#include <cuda_runtime.h>
#include <cuda_bf16.h>
#include <math.h>
#include <stdint.h>

#define N_NODES 20000
#define N_EDGES 640000
#define DIM     128
#define KTOT    512     // [aggX | X | aggH | H]
#define NCOL    512     // 4 gates * 128 outputs, col = o*4 + g
#define MTILES  157     // ceil(20000/128)

// ===================== helpers =====================
__device__ __forceinline__ uint32_t smem_to_u32(const void* p) {
    uint32_t a;
    asm("{ .reg .u64 t; cvta.to.shared.u64 t, %1; cvt.u32.u64 %0, t; }" : "=r"(a) : "l"(p));
    return a;
}
#define CP_ASYNC16(sm, gp) \
    asm volatile("cp.async.cg.shared.global [%0], [%1], 16;" :: "r"(sm), "l"(gp) : "memory")
#define CP_COMMIT() asm volatile("cp.async.commit_group;" ::: "memory")
#define CP_WAIT(n)  asm volatile("cp.async.wait_group %0;" :: "n"(n) : "memory")

#define LDSM_X4(r0, r1, r2, r3, a) \
    asm volatile("ldmatrix.sync.aligned.m8n8.x4.shared.b16 {%0,%1,%2,%3}, [%4];" \
        : "=r"(r0), "=r"(r1), "=r"(r2), "=r"(r3) : "r"(a))

#define MMA16816(d, a, b) \
    asm volatile("mma.sync.aligned.m16n8k16.row.col.f32.bf16.bf16.f32 " \
        "{%0,%1,%2,%3}, {%4,%5,%6,%7}, {%8,%9}, {%0,%1,%2,%3};" \
        : "+f"((d)[0]), "+f"((d)[1]), "+f"((d)[2]), "+f"((d)[3]) \
        : "r"((a)[0]), "r"((a)[1]), "r"((a)[2]), "r"((a)[3]), "r"((b)[0]), "r"((b)[1]))

// ===================== scratch =====================
__device__ int   g_cnt[N_NODES];
__device__ int   g_off[N_NODES + 1];
__device__ int   g_pos[N_NODES];
__device__ int   g_srcp[N_EDGES];
__device__ float g_wp[N_EDGES];
__device__ __nv_bfloat16 g_Ahi[(size_t)N_NODES * KTOT];
__device__ __nv_bfloat16 g_Alo[(size_t)N_NODES * KTOT];
__device__ __nv_bfloat16 g_Bhi[(size_t)NCOL * KTOT];   // [n][k], n = o*4+g
__device__ __nv_bfloat16 g_Blo[(size_t)NCOL * KTOT];

// ===================== CSR build =====================
__global__ void zero_cnt_kernel() {
    int i = blockIdx.x * blockDim.x + threadIdx.x;
    if (i < N_NODES) g_cnt[i] = 0;
}
__global__ void count_kernel(const int* __restrict__ ei) {
    int e = blockIdx.x * blockDim.x + threadIdx.x;
    if (e < N_EDGES) atomicAdd(&g_cnt[ei[N_EDGES + e]], 1);
}
__global__ void scan_kernel() {
    __shared__ int sh[1024];
    __shared__ int s_carry;
    int t = threadIdx.x;
    if (t == 0) s_carry = 0;
    __syncthreads();
    for (int base = 0; base < N_NODES; base += 1024) {
        int i = base + t;
        int v = (i < N_NODES) ? g_cnt[i] : 0;
        sh[t] = v;
        __syncthreads();
        for (int off = 1; off < 1024; off <<= 1) {
            int x = (t >= off) ? sh[t - off] : 0;
            __syncthreads();
            sh[t] += x;
            __syncthreads();
        }
        int excl = s_carry + sh[t] - v;
        if (i < N_NODES) { g_off[i] = excl; g_pos[i] = excl; }
        __syncthreads();
        if (t == 1023) s_carry += sh[1023];
        __syncthreads();
    }
    if (t == 0) g_off[N_NODES] = s_carry;
}
__global__ void scatter_kernel(const int* __restrict__ ei, const float* __restrict__ ew) {
    int e = blockIdx.x * blockDim.x + threadIdx.x;
    if (e < N_EDGES) {
        int d = ei[N_EDGES + e];
        int p = atomicAdd(&g_pos[d], 1);
        g_srcp[p] = ei[e];
        g_wp[p]   = ew[e];
    }
}

// ===================== convert X,H -> bf16 hi/lo (cols 128..255, 384..511) =====================
__global__ void convert_xh_kernel(const float* __restrict__ X, const float* __restrict__ H) {
    int i = blockIdx.x * blockDim.x + threadIdx.x;
    if (i >= N_NODES * DIM) return;
    int r = i >> 7, c = i & 127;
    size_t base = (size_t)r * KTOT;
    float v = X[i];
    __nv_bfloat16 h = __float2bfloat16(v);
    g_Ahi[base + 128 + c] = h;
    g_Alo[base + 128 + c] = __float2bfloat16(v - __bfloat162float(h));
    v = H[i];
    h = __float2bfloat16(v);
    g_Ahi[base + 384 + c] = h;
    g_Alo[base + 384 + c] = __float2bfloat16(v - __bfloat162float(h));
}

// ===================== pack weights B^T[n][k] hi/lo =====================
__global__ void pack_weights_kernel(const float* __restrict__ Wx_l, const float* __restrict__ Wx_r,
                                    const float* __restrict__ Wh_l, const float* __restrict__ Wh_r) {
    int idx = blockIdx.x * blockDim.x + threadIdx.x;
    if (idx >= NCOL * KTOT) return;
    int n = idx >> 9;
    int k = idx & 511;
    int o = n >> 2, g = n & 3;
    int kb = k >> 7, d = k & 127;
    const float* W = (kb == 0) ? Wx_l : (kb == 1) ? Wx_r : (kb == 2) ? Wh_l : Wh_r;
    float v = W[(g * DIM + d) * DIM + o];
    __nv_bfloat16 h = __float2bfloat16(v);
    g_Bhi[idx] = h;
    g_Blo[idx] = __float2bfloat16(v - __bfloat162float(h));
}

// ===================== aggregation: 1 warp/node, bf16 gather =====================
__global__ void aggregate_kernel() {
    int warp = (blockIdx.x * blockDim.x + threadIdx.x) >> 5;
    int lane = threadIdx.x & 31;
    if (warp >= N_NODES) return;
    int beg = g_off[warp], end = g_off[warp + 1];
    float ax[4] = {0.f, 0.f, 0.f, 0.f};
    float ah[4] = {0.f, 0.f, 0.f, 0.f};
    for (int e = beg; e < end; e++) {
        int   s = g_srcp[e];
        float w = g_wp[e];
        const uint2* px = (const uint2*)(g_Ahi + (size_t)s * KTOT + 128) + lane;
        const uint2* ph = (const uint2*)(g_Ahi + (size_t)s * KTOT + 384) + lane;
        uint2 xv = __ldg(px);
        uint2 hv = __ldg(ph);
        float2 x01 = __bfloat1622float2(*(const __nv_bfloat162*)&xv.x);
        float2 x23 = __bfloat1622float2(*(const __nv_bfloat162*)&xv.y);
        float2 h01 = __bfloat1622float2(*(const __nv_bfloat162*)&hv.x);
        float2 h23 = __bfloat1622float2(*(const __nv_bfloat162*)&hv.y);
        ax[0] = fmaf(w, x01.x, ax[0]); ax[1] = fmaf(w, x01.y, ax[1]);
        ax[2] = fmaf(w, x23.x, ax[2]); ax[3] = fmaf(w, x23.y, ax[3]);
        ah[0] = fmaf(w, h01.x, ah[0]); ah[1] = fmaf(w, h01.y, ah[1]);
        ah[2] = fmaf(w, h23.x, ah[2]); ah[3] = fmaf(w, h23.y, ah[3]);
    }
    float inv = 1.0f / fmaxf((float)(end - beg), 1.0f);
    size_t base = (size_t)warp * KTOT;
    __nv_bfloat16 hh[4], ll[4];
#pragma unroll
    for (int j = 0; j < 4; j++) {
        float v = ax[j] * inv;
        hh[j] = __float2bfloat16(v);
        ll[j] = __float2bfloat16(v - __bfloat162float(hh[j]));
    }
    {
        __nv_bfloat162* ph2 = (__nv_bfloat162*)(g_Ahi + base + lane * 4);
        __nv_bfloat162* pl2 = (__nv_bfloat162*)(g_Alo + base + lane * 4);
        ph2[0] = __nv_bfloat162(hh[0], hh[1]); ph2[1] = __nv_bfloat162(hh[2], hh[3]);
        pl2[0] = __nv_bfloat162(ll[0], ll[1]); pl2[1] = __nv_bfloat162(ll[2], ll[3]);
    }
#pragma unroll
    for (int j = 0; j < 4; j++) {
        float v = ah[j] * inv;
        hh[j] = __float2bfloat16(v);
        ll[j] = __float2bfloat16(v - __bfloat162float(hh[j]));
    }
    {
        __nv_bfloat162* ph2 = (__nv_bfloat162*)(g_Ahi + base + 256 + lane * 4);
        __nv_bfloat162* pl2 = (__nv_bfloat162*)(g_Alo + base + 256 + lane * 4);
        ph2[0] = __nv_bfloat162(hh[0], hh[1]); ph2[1] = __nv_bfloat162(hh[2], hh[3]);
        pl2[0] = __nv_bfloat162(ll[0], ll[1]); pl2[1] = __nv_bfloat162(ll[2], ll[3]);
    }
}

// ===================== warp-MMA GEMM (split-bf16 x3) + fused LSTM =====================
// Block 128x128, 256 threads (8 warps, 2x4). K: 16 tiles of 32, double-buffered.
// SMEM per buffer: 4 tiles (Ahi,Alo,Bhi,Blo), each 128 rows x 80B (32 bf16 + 16B pad).
#define TILE_B   10240            // 128*80
#define BUF_B    (4 * TILE_B)     // 40960
#define GEMM_SMEM (2 * BUF_B)     // 81920 (also covers epilogue D: 128*132*4 = 67584)
#define DSTRIDE  132

__global__ void __launch_bounds__(256, 1) gemm_lstm_kernel(
    const float* __restrict__ C,
    const float* __restrict__ bx, const float* __restrict__ bh, const float* __restrict__ bg,
    const float* __restrict__ wc,
    float* __restrict__ outH, float* __restrict__ outC)
{
    extern __shared__ char sm[];
    uint32_t smb = smem_to_u32(sm);

    int tid = threadIdx.x;
    int wid = tid >> 5, lid = tid & 31;
    int ntile = blockIdx.x;        // 0..3
    int row0  = blockIdx.y * 128;

    // ---- load mapping (cp.async): thread -> row=tid>>1, two 16B segs ----
    int lrow = tid >> 1;
    int seg0 = (tid & 1) * 2;
    int arow = row0 + lrow; if (arow >= N_NODES) arow = N_NODES - 1;
    int brow = ntile * 128 + lrow;
    const __nv_bfloat16* gAhi = g_Ahi + (size_t)arow * KTOT;
    const __nv_bfloat16* gAlo = g_Alo + (size_t)arow * KTOT;
    const __nv_bfloat16* gBhi = g_Bhi + (size_t)brow * KTOT;
    const __nv_bfloat16* gBlo = g_Blo + (size_t)brow * KTOT;
    uint32_t sm_row = smb + lrow * 80 + seg0 * 16;

    // ---- warp tiling ----
    int mw = (wid >> 2) * 64;      // warp M offset
    int nw = (wid & 3) * 32;       // warp N offset
    // ldmatrix lane offsets
    int a_r = ((lid >> 3) & 1) * 8 + (lid & 7);
    int a_k = (lid >> 4) * 8;
    int b_r = (lid >> 4) * 8 + (lid & 7);
    int b_k = ((lid >> 3) & 1) * 8;

    float acc[4][4][4];
#pragma unroll
    for (int i = 0; i < 4; i++)
#pragma unroll
        for (int j = 0; j < 4; j++)
#pragma unroll
            for (int q = 0; q < 4; q++) acc[i][j][q] = 0.f;

    // ---- prologue: load k-tile 0 into buf 0 ----
#pragma unroll
    for (int j = 0; j < 2; j++) {
        int kb = (seg0 + j) * 8;                   // bf16 offset within tile
        uint32_t so = sm_row + j * 16;
        CP_ASYNC16(so,              gAhi + kb);
        CP_ASYNC16(so + TILE_B,     gAlo + kb);
        CP_ASYNC16(so + 2 * TILE_B, gBhi + kb);
        CP_ASYNC16(so + 3 * TILE_B, gBlo + kb);
    }
    CP_COMMIT();

    int buf = 0;
    for (int kt = 0; kt < 16; kt++) {
        if (kt < 15) {
            int k0 = (kt + 1) * 32;
            uint32_t sb = sm_row + (buf ^ 1) * BUF_B;
#pragma unroll
            for (int j = 0; j < 2; j++) {
                int kb = k0 + (seg0 + j) * 8;
                uint32_t so = sb + j * 16;
                CP_ASYNC16(so,              gAhi + kb);
                CP_ASYNC16(so + TILE_B,     gAlo + kb);
                CP_ASYNC16(so + 2 * TILE_B, gBhi + kb);
                CP_ASYNC16(so + 3 * TILE_B, gBlo + kb);
            }
            CP_COMMIT();
            CP_WAIT(1);
        } else {
            CP_WAIT(0);
        }
        __syncthreads();

        uint32_t base = smb + buf * BUF_B;
        uint32_t aAh = base + (mw + a_r) * 80 + a_k * 2;
        uint32_t aAl = aAh + TILE_B;
        uint32_t aBh = base + 2 * TILE_B + (nw + b_r) * 80 + b_k * 2;
        uint32_t aBl = aBh + TILE_B;

#pragma unroll
        for (int ks = 0; ks < 2; ks++) {
            uint32_t koff = ks * 32;   // 16 bf16 = 32B
            uint32_t Ah[4][4], Al[4][4], Bh[4][2], Bl[4][2];
#pragma unroll
            for (int mi = 0; mi < 4; mi++) {
                LDSM_X4(Ah[mi][0], Ah[mi][1], Ah[mi][2], Ah[mi][3], aAh + mi * 1280 + koff);
                LDSM_X4(Al[mi][0], Al[mi][1], Al[mi][2], Al[mi][3], aAl + mi * 1280 + koff);
            }
#pragma unroll
            for (int nj = 0; nj < 2; nj++) {
                LDSM_X4(Bh[2 * nj][0], Bh[2 * nj][1], Bh[2 * nj + 1][0], Bh[2 * nj + 1][1],
                        aBh + nj * 1280 + koff);
                LDSM_X4(Bl[2 * nj][0], Bl[2 * nj][1], Bl[2 * nj + 1][0], Bl[2 * nj + 1][1],
                        aBl + nj * 1280 + koff);
            }
#pragma unroll
            for (int mi = 0; mi < 4; mi++)
#pragma unroll
                for (int ni = 0; ni < 4; ni++) {
                    MMA16816(acc[mi][ni], Ah[mi], Bh[ni]);
                    MMA16816(acc[mi][ni], Al[mi], Bh[ni]);
                    MMA16816(acc[mi][ni], Ah[mi], Bl[ni]);
                }
        }
        __syncthreads();   // protect buffer before next overwrite
        buf ^= 1;
    }

    // ---- epilogue: acc -> smem D[128][132] ----
    float* sD = (float*)sm;
    {
        int r0 = mw + (lid >> 2);
        int c0 = nw + (lid & 3) * 2;
#pragma unroll
        for (int mi = 0; mi < 4; mi++)
#pragma unroll
            for (int ni = 0; ni < 4; ni++) {
                int rr = r0 + mi * 16, cc = c0 + ni * 8;
                sD[rr * DSTRIDE + cc]           = acc[mi][ni][0];
                sD[rr * DSTRIDE + cc + 1]       = acc[mi][ni][1];
                sD[(rr + 8) * DSTRIDE + cc]     = acc[mi][ni][2];
                sD[(rr + 8) * DSTRIDE + cc + 1] = acc[mi][ni][3];
            }
    }
    __syncthreads();

    // ---- fused LSTM: thread -> row=tid>>1, 16 outputs ----
    {
        int row = tid >> 1;
        int r = row0 + row;
        if (r < N_NODES) {
            int ob = (tid & 1) * 16;               // local o base (0 or 16)
            int o0 = ntile * 32 + ob;              // global o base
#pragma unroll 4
            for (int j = 0; j < 16; j += 4) {
                float4 cold4 = *(const float4*)&C[(size_t)r * DIM + o0 + j];
                float co[4] = {cold4.x, cold4.y, cold4.z, cold4.w};
                float hnew[4], cnew[4];
#pragma unroll
                for (int q = 0; q < 4; q++) {
                    int o = o0 + j + q;
                    float4 gq = *(float4*)&sD[row * DSTRIDE + (ob + j + q) * 4];
                    float gI = gq.x + bx[0 * DIM + o] + bh[0 * DIM + o] + bg[0 * DIM + o] + wc[0 * DIM + o] * co[q];
                    float gF = gq.y + bx[1 * DIM + o] + bh[1 * DIM + o] + bg[1 * DIM + o] + wc[1 * DIM + o] * co[q];
                    float gT = gq.z + bx[2 * DIM + o] + bh[2 * DIM + o] + bg[2 * DIM + o];
                    float I = 1.f / (1.f + expf(-gI));
                    float F = 1.f / (1.f + expf(-gF));
                    float T = tanhf(gT);
                    float cn = fmaf(F, co[q], I * T);
                    float gO = gq.w + bx[3 * DIM + o] + bh[3 * DIM + o] + bg[3 * DIM + o] + wc[2 * DIM + o] * cn;
                    float O = 1.f / (1.f + expf(-gO));
                    hnew[q] = O * tanhf(cn);
                    cnew[q] = cn;
                }
                *(float4*)&outH[(size_t)r * DIM + o0 + j] = make_float4(hnew[0], hnew[1], hnew[2], hnew[3]);
                *(float4*)&outC[(size_t)r * DIM + o0 + j] = make_float4(cnew[0], cnew[1], cnew[2], cnew[3]);
            }
        }
    }
}

// ===================== launch =====================
extern "C" void kernel_launch(void* const* d_in, const int* in_sizes, int n_in,
                              void* d_out, int out_size) {
    const float* X    = (const float*)d_in[0];
    const int*   ei   = (const int*)  d_in[1];
    const float* ew   = (const float*)d_in[2];
    const float* H    = (const float*)d_in[3];
    const float* C    = (const float*)d_in[4];
    const float* Wx_l = (const float*)d_in[5];
    const float* Wx_r = (const float*)d_in[6];
    const float* bx   = (const float*)d_in[7];
    const float* Wh_l = (const float*)d_in[8];
    const float* Wh_r = (const float*)d_in[9];
    const float* bh   = (const float*)d_in[10];
    const float* wc   = (const float*)d_in[11];
    const float* bg   = (const float*)d_in[12];

    float* outH = (float*)d_out;
    float* outC = outH + (size_t)N_NODES * DIM;

    static int smem_set = 0;
    if (!smem_set) {
        cudaFuncSetAttribute(gemm_lstm_kernel, cudaFuncAttributeMaxDynamicSharedMemorySize, GEMM_SMEM);
        smem_set = 1;
    }

    zero_cnt_kernel<<<(N_NODES + 255) / 256, 256>>>();
    count_kernel<<<(N_EDGES + 255) / 256, 256>>>(ei);
    scan_kernel<<<1, 1024>>>();
    scatter_kernel<<<(N_EDGES + 255) / 256, 256>>>(ei, ew);
    convert_xh_kernel<<<(N_NODES * DIM + 255) / 256, 256>>>(X, H);
    pack_weights_kernel<<<(NCOL * KTOT + 255) / 256, 256>>>(Wx_l, Wx_r, Wh_l, Wh_r);
    aggregate_kernel<<<(N_NODES * 32 + 255) / 256, 256>>>();

    dim3 grid(4, MTILES);
    gemm_lstm_kernel<<<grid, 256, GEMM_SMEM>>>(C, bx, bh, bg, wc, outH, outC);
}

// round 4
// speedup vs baseline: 1.7316x; 1.1440x over previous
#include <cuda_runtime.h>
#include <cuda_bf16.h>
#include <math.h>
#include <stdint.h>

#define N_NODES 20000
#define N_EDGES 640000
#define DIM     128
#define KTOT    512     // [aggX | X | aggH | H]
#define NCOL    512     // 4 gates * 128 outputs, col = o*4 + g
#define MTILES  157     // ceil(20000/128)

// ===================== helpers =====================
__device__ __forceinline__ uint32_t smem_to_u32(const void* p) {
    uint32_t a;
    asm("{ .reg .u64 t; cvta.to.shared.u64 t, %1; cvt.u32.u64 %0, t; }" : "=r"(a) : "l"(p));
    return a;
}
#define CP_ASYNC16(sm, gp) \
    asm volatile("cp.async.cg.shared.global [%0], [%1], 16;" :: "r"(sm), "l"(gp) : "memory")
#define CP_COMMIT() asm volatile("cp.async.commit_group;" ::: "memory")
#define CP_WAIT(n)  asm volatile("cp.async.wait_group %0;" :: "n"(n) : "memory")

#define F2TF32(u, f) asm volatile("cvt.rna.tf32.f32 %0, %1;" : "=r"(u) : "f"(f))

#define MMA_TF32(d, a, b) \
    asm volatile("mma.sync.aligned.m16n8k8.row.col.f32.tf32.tf32.f32 " \
        "{%0,%1,%2,%3}, {%4,%5,%6,%7}, {%8,%9}, {%0,%1,%2,%3};" \
        : "+f"((d)[0]), "+f"((d)[1]), "+f"((d)[2]), "+f"((d)[3]) \
        : "r"((a)[0]), "r"((a)[1]), "r"((a)[2]), "r"((a)[3]), "r"((b)[0]), "r"((b)[1]))

// ===================== scratch =====================
__device__ int   g_cnt[N_NODES];
__device__ int   g_off[N_NODES + 1];
__device__ int   g_pos[N_NODES];
__device__ int   g_srcp[N_EDGES];
__device__ float g_wp[N_EDGES];
__device__ float g_aggX[(size_t)N_NODES * DIM];
__device__ float g_aggH[(size_t)N_NODES * DIM];
__device__ float g_B[(size_t)NCOL * KTOT];                 // fp32 [n][k], n = o*4+g
__device__ __nv_bfloat16 g_XHb16[(size_t)N_NODES * 256];   // [node]: 128 X | 128 H (gather copy)

// ===================== CSR build =====================
__global__ void zero_cnt_kernel() {
    int i = blockIdx.x * blockDim.x + threadIdx.x;
    if (i < N_NODES) g_cnt[i] = 0;
}
__global__ void count_kernel(const int* __restrict__ ei) {
    int e = blockIdx.x * blockDim.x + threadIdx.x;
    if (e < N_EDGES) atomicAdd(&g_cnt[ei[N_EDGES + e]], 1);
}
// coarsened single-block scan: 1024 threads x 20 elems
__global__ void scan_kernel() {
    const int PER = 20;
    int t = threadIdx.x;
    int base = t * PER;
    int loc[PER];
    int sum = 0;
#pragma unroll
    for (int j = 0; j < PER; j++) {
        int i = base + j;
        int v = (i < N_NODES) ? g_cnt[i] : 0;
        loc[j] = sum;
        sum += v;
    }
    int lane = t & 31, warp = t >> 5;
    int x = sum;
#pragma unroll
    for (int o = 1; o < 32; o <<= 1) {
        int y = __shfl_up_sync(0xFFFFFFFFu, x, o);
        if (lane >= o) x += y;
    }
    __shared__ int wsum[32];
    if (lane == 31) wsum[warp] = x;
    __syncthreads();
    if (warp == 0) {
        int w = wsum[lane];
#pragma unroll
        for (int o = 1; o < 32; o <<= 1) {
            int y = __shfl_up_sync(0xFFFFFFFFu, w, o);
            if (lane >= o) w += y;
        }
        wsum[lane] = w;
    }
    __syncthreads();
    int warpbase = (warp > 0) ? wsum[warp - 1] : 0;
    int excl = warpbase + x - sum;
#pragma unroll
    for (int j = 0; j < PER; j++) {
        int i = base + j;
        if (i < N_NODES) {
            int p = excl + loc[j];
            g_off[i] = p;
            g_pos[i] = p;
        }
    }
    if (t == 1023) g_off[N_NODES] = warpbase + x;
}
__global__ void scatter_kernel(const int* __restrict__ ei, const float* __restrict__ ew) {
    int e = blockIdx.x * blockDim.x + threadIdx.x;
    if (e < N_EDGES) {
        int d = ei[N_EDGES + e];
        int p = atomicAdd(&g_pos[d], 1);
        g_srcp[p] = ei[e];
        g_wp[p]   = ew[e];
    }
}

// ===================== prep: bf16 gather copy of X,H + fp32 weight pack =====================
#define CONV_N (N_NODES * DIM)
#define PACK_N (NCOL * KTOT)
__global__ void prep_kernel(const float* __restrict__ X, const float* __restrict__ H,
                            const float* __restrict__ Wx_l, const float* __restrict__ Wx_r,
                            const float* __restrict__ Wh_l, const float* __restrict__ Wh_r) {
    int idx = blockIdx.x * blockDim.x + threadIdx.x;
    if (idx < CONV_N) {
        int r = idx >> 7, c = idx & 127;
        size_t base = (size_t)r * 256;
        g_XHb16[base + c]       = __float2bfloat16(X[idx]);
        g_XHb16[base + 128 + c] = __float2bfloat16(H[idx]);
    } else {
        int j = idx - CONV_N;
        if (j < PACK_N) {
            int n = j >> 9;
            int k = j & 511;
            int o = n >> 2, g = n & 3;
            int kb = k >> 7, d = k & 127;
            const float* W = (kb == 0) ? Wx_l : (kb == 1) ? Wx_r : (kb == 2) ? Wh_l : Wh_r;
            g_B[j] = W[(g * DIM + d) * DIM + o];
        }
    }
}

// ===================== aggregation: 1 warp/node, bf16 gather, fp32 output =====================
__global__ void aggregate_kernel() {
    int warp = (blockIdx.x * blockDim.x + threadIdx.x) >> 5;
    int lane = threadIdx.x & 31;
    if (warp >= N_NODES) return;
    int beg = g_off[warp], end = g_off[warp + 1];
    float ax[4] = {0.f, 0.f, 0.f, 0.f};
    float ah[4] = {0.f, 0.f, 0.f, 0.f};
    for (int e = beg; e < end; e++) {
        int   s = g_srcp[e];
        float w = g_wp[e];
        const uint2* px = (const uint2*)(g_XHb16 + (size_t)s * 256) + lane;
        const uint2* ph = (const uint2*)(g_XHb16 + (size_t)s * 256 + 128) + lane;
        uint2 xv = __ldg(px);
        uint2 hv = __ldg(ph);
        float2 x01 = __bfloat1622float2(*(const __nv_bfloat162*)&xv.x);
        float2 x23 = __bfloat1622float2(*(const __nv_bfloat162*)&xv.y);
        float2 h01 = __bfloat1622float2(*(const __nv_bfloat162*)&hv.x);
        float2 h23 = __bfloat1622float2(*(const __nv_bfloat162*)&hv.y);
        ax[0] = fmaf(w, x01.x, ax[0]); ax[1] = fmaf(w, x01.y, ax[1]);
        ax[2] = fmaf(w, x23.x, ax[2]); ax[3] = fmaf(w, x23.y, ax[3]);
        ah[0] = fmaf(w, h01.x, ah[0]); ah[1] = fmaf(w, h01.y, ah[1]);
        ah[2] = fmaf(w, h23.x, ah[2]); ah[3] = fmaf(w, h23.y, ah[3]);
    }
    float inv = 1.0f / fmaxf((float)(end - beg), 1.0f);
    *(float4*)(g_aggX + (size_t)warp * DIM + lane * 4) =
        make_float4(ax[0] * inv, ax[1] * inv, ax[2] * inv, ax[3] * inv);
    *(float4*)(g_aggH + (size_t)warp * DIM + lane * 4) =
        make_float4(ah[0] * inv, ah[1] * inv, ah[2] * inv, ah[3] * inv);
}

// ===================== tf32 warp-MMA GEMM + fused LSTM =====================
// Block 128x128, 256 threads (8 warps 2x4), warp tile 64x32.
// K: 16 tiles of 32, double-buffered. SMEM rows padded: 32 fp32 + 4 pad = 144B.
#define ROW_B    144
#define ATILE_B  (128 * ROW_B)        // 18432
#define STAGE_B  (2 * ATILE_B)        // 36864 (A then B)
#define GEMM_SMEM (2 * STAGE_B)       // 73728 (epilogue D 128*132*4 = 67584 fits)
#define DSTRIDE  132

__global__ void __launch_bounds__(256, 1) gemm_lstm_kernel(
    const float* __restrict__ X, const float* __restrict__ H, const float* __restrict__ C,
    const float* __restrict__ bx, const float* __restrict__ bh, const float* __restrict__ bg,
    const float* __restrict__ wc,
    float* __restrict__ outH, float* __restrict__ outC)
{
    extern __shared__ char sm[];
    uint32_t smb = smem_to_u32(sm);

    int tid = threadIdx.x;
    int wid = tid >> 5, lid = tid & 31;
    int ntile = blockIdx.x;        // 0..3
    int row0  = blockIdx.y * 128;

    // ---- cp.async mapping: thread -> row = tid>>1, half = tid&1 (16 floats = 4 segs) ----
    int lrow = tid >> 1;
    int half = tid & 1;
    int arow = row0 + lrow; if (arow >= N_NODES) arow = N_NODES - 1;
    int brow = ntile * 128 + lrow;
    uint32_t dst_off = (uint32_t)lrow * ROW_B + half * 64;   // within tile

    const float* aggXp = g_aggX;
    const float* aggHp = g_aggH;
    const float* Bp    = g_B + (size_t)brow * KTOT;

    // ---- warp tiling ----
    int mw = (wid >> 2) * 64;
    int nw = (wid & 3) * 32;
    int qr = lid >> 2;   // 0..7
    int qc = lid & 3;    // 0..3

    float acc[4][4][4];
#pragma unroll
    for (int i = 0; i < 4; i++)
#pragma unroll
        for (int j = 0; j < 4; j++)
#pragma unroll
            for (int q = 0; q < 4; q++) acc[i][j][q] = 0.f;

    // ---- prologue: load kt=0 into stage 0 ----
    {
        const float* srcA = aggXp + (size_t)arow * DIM;   // kt=0 -> chunk 0, col0 0
        const float* sa = srcA + half * 16;
        const float* sb = Bp + half * 16;
        uint32_t da = smb + dst_off;
        uint32_t db = smb + ATILE_B + dst_off;
#pragma unroll
        for (int j = 0; j < 4; j++) {
            CP_ASYNC16(da + j * 16, sa + j * 4);
            CP_ASYNC16(db + j * 16, sb + j * 4);
        }
        CP_COMMIT();
    }

    int buf = 0;
    for (int kt = 0; kt < 16; kt++) {
        CP_WAIT(0);
        __syncthreads();
        if (kt < 15) {
            int k1 = (kt + 1);
            int chunk = k1 >> 2;
            int col0 = (k1 & 3) * 32;
            const float* srcA = (chunk == 0) ? (aggXp + (size_t)arow * DIM)
                              : (chunk == 1) ? (X + (size_t)arow * DIM)
                              : (chunk == 2) ? (aggHp + (size_t)arow * DIM)
                                             : (H + (size_t)arow * DIM);
            const float* sa = srcA + col0 + half * 16;
            const float* sb = Bp + k1 * 32 + half * 16;
            uint32_t sbb = smb + (buf ^ 1) * STAGE_B;
            uint32_t da = sbb + dst_off;
            uint32_t db = sbb + ATILE_B + dst_off;
#pragma unroll
            for (int j = 0; j < 4; j++) {
                CP_ASYNC16(da + j * 16, sa + j * 4);
                CP_ASYNC16(db + j * 16, sb + j * 4);
            }
            CP_COMMIT();
        }

        const char* smA = sm + buf * STAGE_B;
        const char* smB = smA + ATILE_B;

#pragma unroll
        for (int ks = 0; ks < 4; ks++) {
            int kc = ks * 8;
            uint32_t a[4][4], b[4][2];
#pragma unroll
            for (int mi = 0; mi < 4; mi++) {
                const char* base = smA + (mw + mi * 16 + qr) * ROW_B + (kc + qc) * 4;
                float f0 = *(const float*)(base);
                float f1 = *(const float*)(base + 8 * ROW_B);
                float f2 = *(const float*)(base + 16);
                float f3 = *(const float*)(base + 8 * ROW_B + 16);
                F2TF32(a[mi][0], f0); F2TF32(a[mi][1], f1);
                F2TF32(a[mi][2], f2); F2TF32(a[mi][3], f3);
            }
#pragma unroll
            for (int ni = 0; ni < 4; ni++) {
                const char* base = smB + (nw + ni * 8 + qr) * ROW_B + (kc + qc) * 4;
                float f0 = *(const float*)(base);
                float f1 = *(const float*)(base + 16);
                F2TF32(b[ni][0], f0); F2TF32(b[ni][1], f1);
            }
#pragma unroll
            for (int mi = 0; mi < 4; mi++)
#pragma unroll
                for (int ni = 0; ni < 4; ni++)
                    MMA_TF32(acc[mi][ni], a[mi], b[ni]);
        }
        buf ^= 1;
    }
    __syncthreads();

    // ---- epilogue: acc -> smem D[128][132] ----
    float* sD = (float*)sm;
    {
        int r0 = mw + qr;
        int c0 = nw + qc * 2;
#pragma unroll
        for (int mi = 0; mi < 4; mi++)
#pragma unroll
            for (int ni = 0; ni < 4; ni++) {
                int rr = r0 + mi * 16, cc = c0 + ni * 8;
                sD[rr * DSTRIDE + cc]           = acc[mi][ni][0];
                sD[rr * DSTRIDE + cc + 1]       = acc[mi][ni][1];
                sD[(rr + 8) * DSTRIDE + cc]     = acc[mi][ni][2];
                sD[(rr + 8) * DSTRIDE + cc + 1] = acc[mi][ni][3];
            }
    }
    __syncthreads();

    // ---- fused LSTM: thread -> row = tid>>1, 16 outputs ----
    {
        int row = tid >> 1;
        int r = row0 + row;
        if (r < N_NODES) {
            int ob = (tid & 1) * 16;
            int o0 = ntile * 32 + ob;
#pragma unroll 4
            for (int j = 0; j < 16; j += 4) {
                float4 cold4 = *(const float4*)&C[(size_t)r * DIM + o0 + j];
                float co[4] = {cold4.x, cold4.y, cold4.z, cold4.w};
                float hnew[4], cnew[4];
#pragma unroll
                for (int q = 0; q < 4; q++) {
                    int o = o0 + j + q;
                    float4 gq = *(float4*)&sD[row * DSTRIDE + (ob + j + q) * 4];
                    float gI = gq.x + bx[0 * DIM + o] + bh[0 * DIM + o] + bg[0 * DIM + o] + wc[0 * DIM + o] * co[q];
                    float gF = gq.y + bx[1 * DIM + o] + bh[1 * DIM + o] + bg[1 * DIM + o] + wc[1 * DIM + o] * co[q];
                    float gT = gq.z + bx[2 * DIM + o] + bh[2 * DIM + o] + bg[2 * DIM + o];
                    float I = 1.f / (1.f + expf(-gI));
                    float F = 1.f / (1.f + expf(-gF));
                    float T = tanhf(gT);
                    float cn = fmaf(F, co[q], I * T);
                    float gO = gq.w + bx[3 * DIM + o] + bh[3 * DIM + o] + bg[3 * DIM + o] + wc[2 * DIM + o] * cn;
                    float O = 1.f / (1.f + expf(-gO));
                    hnew[q] = O * tanhf(cn);
                    cnew[q] = cn;
                }
                *(float4*)&outH[(size_t)r * DIM + o0 + j] = make_float4(hnew[0], hnew[1], hnew[2], hnew[3]);
                *(float4*)&outC[(size_t)r * DIM + o0 + j] = make_float4(cnew[0], cnew[1], cnew[2], cnew[3]);
            }
        }
    }
}

// ===================== launch =====================
extern "C" void kernel_launch(void* const* d_in, const int* in_sizes, int n_in,
                              void* d_out, int out_size) {
    const float* X    = (const float*)d_in[0];
    const int*   ei   = (const int*)  d_in[1];
    const float* ew   = (const float*)d_in[2];
    const float* H    = (const float*)d_in[3];
    const float* C    = (const float*)d_in[4];
    const float* Wx_l = (const float*)d_in[5];
    const float* Wx_r = (const float*)d_in[6];
    const float* bx   = (const float*)d_in[7];
    const float* Wh_l = (const float*)d_in[8];
    const float* Wh_r = (const float*)d_in[9];
    const float* bh   = (const float*)d_in[10];
    const float* wc   = (const float*)d_in[11];
    const float* bg   = (const float*)d_in[12];

    float* outH = (float*)d_out;
    float* outC = outH + (size_t)N_NODES * DIM;

    cudaFuncSetAttribute(gemm_lstm_kernel, cudaFuncAttributeMaxDynamicSharedMemorySize, GEMM_SMEM);

    zero_cnt_kernel<<<(N_NODES + 255) / 256, 256>>>();
    count_kernel<<<(N_EDGES + 255) / 256, 256>>>(ei);
    scan_kernel<<<1, 1024>>>();
    scatter_kernel<<<(N_EDGES + 255) / 256, 256>>>(ei, ew);
    prep_kernel<<<(CONV_N + PACK_N + 255) / 256, 256>>>(X, H, Wx_l, Wx_r, Wh_l, Wh_r);
    aggregate_kernel<<<(N_NODES * 32 + 255) / 256, 256>>>();

    dim3 grid(4, MTILES);
    gemm_lstm_kernel<<<grid, 256, GEMM_SMEM>>>(X, H, C, bx, bh, bg, wc, outH, outC);
}

// round 5
// speedup vs baseline: 1.7911x; 1.0343x over previous
#include <cuda_runtime.h>
#include <cuda_bf16.h>
#include <math.h>
#include <stdint.h>

#define N_NODES 20000
#define N_EDGES 640000
#define DIM     128
#define KTOT    512     // A cols: [aggX | X | aggH | H]
#define NCOL    512     // 4 gates * 128 outputs, col = o*4 + g
#define MTILES  157     // ceil(20000/128)

// ===================== helpers =====================
__device__ __forceinline__ uint32_t smem_to_u32(const void* p) {
    uint32_t a;
    asm("{ .reg .u64 t; cvta.to.shared.u64 t, %1; cvt.u32.u64 %0, t; }" : "=r"(a) : "l"(p));
    return a;
}
#define CP_ASYNC16(sm, gp) \
    asm volatile("cp.async.cg.shared.global [%0], [%1], 16;" :: "r"(sm), "l"(gp) : "memory")
#define CP_COMMIT() asm volatile("cp.async.commit_group;" ::: "memory")
#define CP_WAIT(n)  asm volatile("cp.async.wait_group %0;" :: "n"(n) : "memory")

#define F2TF32(u, f) asm volatile("cvt.rna.tf32.f32 %0, %1;" : "=r"(u) : "f"(f))
__device__ __forceinline__ float tf32f(float f) { uint32_t u; F2TF32(u, f); return __uint_as_float(u); }

#define MMA_TF32(d, a, b) \
    asm volatile("mma.sync.aligned.m16n8k8.row.col.f32.tf32.tf32.f32 " \
        "{%0,%1,%2,%3}, {%4,%5,%6,%7}, {%8,%9}, {%0,%1,%2,%3};" \
        : "+f"((d)[0]), "+f"((d)[1]), "+f"((d)[2]), "+f"((d)[3]) \
        : "r"((a)[0]), "r"((a)[1]), "r"((a)[2]), "r"((a)[3]), "r"((b)[0]), "r"((b)[1]))

// ===================== scratch =====================
__device__ int   g_cnt[N_NODES];
__device__ int   g_off[N_NODES + 1];
__device__ int   g_pos[N_NODES];
__device__ uint2 g_edge[N_EDGES];                          // {src, weight bits}
__device__ float g_A[(size_t)N_NODES * KTOT];              // tf32-rounded A matrix
__device__ float g_B[(size_t)NCOL * KTOT];                 // tf32-rounded B^T [n][k]
__device__ __nv_bfloat16 g_XHb16[(size_t)N_NODES * 256];   // bf16 gather copy: 128 X | 128 H

// ===================== CSR build =====================
__global__ void zero_cnt_kernel() {
    int i = blockIdx.x * blockDim.x + threadIdx.x;
    if (i < N_NODES) g_cnt[i] = 0;
}
__global__ void count_kernel(const int* __restrict__ ei) {
    int e = blockIdx.x * blockDim.x + threadIdx.x;
    if (e < N_EDGES) atomicAdd(&g_cnt[ei[N_EDGES + e]], 1);
}
// coarsened single-block scan: 1024 threads x 20 elems
__global__ void scan_kernel() {
    const int PER = 20;
    int t = threadIdx.x;
    int base = t * PER;
    int loc[PER];
    int sum = 0;
#pragma unroll
    for (int j = 0; j < PER; j++) {
        int i = base + j;
        int v = (i < N_NODES) ? g_cnt[i] : 0;
        loc[j] = sum;
        sum += v;
    }
    int lane = t & 31, warp = t >> 5;
    int x = sum;
#pragma unroll
    for (int o = 1; o < 32; o <<= 1) {
        int y = __shfl_up_sync(0xFFFFFFFFu, x, o);
        if (lane >= o) x += y;
    }
    __shared__ int wsum[32];
    if (lane == 31) wsum[warp] = x;
    __syncthreads();
    if (warp == 0) {
        int w = wsum[lane];
#pragma unroll
        for (int o = 1; o < 32; o <<= 1) {
            int y = __shfl_up_sync(0xFFFFFFFFu, w, o);
            if (lane >= o) w += y;
        }
        wsum[lane] = w;
    }
    __syncthreads();
    int warpbase = (warp > 0) ? wsum[warp - 1] : 0;
    int excl = warpbase + x - sum;
#pragma unroll
    for (int j = 0; j < PER; j++) {
        int i = base + j;
        if (i < N_NODES) {
            int p = excl + loc[j];
            g_off[i] = p;
            g_pos[i] = p;
        }
    }
    if (t == 1023) g_off[N_NODES] = warpbase + x;
}
__global__ void scatter_kernel(const int* __restrict__ ei, const float* __restrict__ ew) {
    int e = blockIdx.x * blockDim.x + threadIdx.x;
    if (e < N_EDGES) {
        int d = ei[N_EDGES + e];
        int p = atomicAdd(&g_pos[d], 1);
        g_edge[p] = make_uint2((uint32_t)ei[e], __float_as_uint(ew[e]));
    }
}

// ===================== prep: bf16 gather copy + tf32 X/H into g_A + tf32 B pack =====================
#define CONV_N (N_NODES * DIM)
#define PACK_N (NCOL * KTOT)
__global__ void prep_kernel(const float* __restrict__ X, const float* __restrict__ H,
                            const float* __restrict__ Wx_l, const float* __restrict__ Wx_r,
                            const float* __restrict__ Wh_l, const float* __restrict__ Wh_r) {
    int idx = blockIdx.x * blockDim.x + threadIdx.x;
    if (idx < CONV_N) {
        int r = idx >> 7, c = idx & 127;
        float xv = X[idx], hv = H[idx];
        size_t b16 = (size_t)r * 256;
        g_XHb16[b16 + c]       = __float2bfloat16(xv);
        g_XHb16[b16 + 128 + c] = __float2bfloat16(hv);
        size_t ba = (size_t)r * KTOT;
        g_A[ba + 128 + c] = tf32f(xv);
        g_A[ba + 384 + c] = tf32f(hv);
    } else {
        int j = idx - CONV_N;
        if (j < PACK_N) {
            int n = j >> 9;
            int k = j & 511;
            int o = n >> 2, g = n & 3;
            int kb = k >> 7, d = k & 127;
            const float* W = (kb == 0) ? Wx_l : (kb == 1) ? Wx_r : (kb == 2) ? Wh_l : Wh_r;
            g_B[j] = tf32f(W[(g * DIM + d) * DIM + o]);
        }
    }
}

// ===================== aggregation: 1 warp/node, bf16 gather, tf32 out into g_A =====================
__global__ void aggregate_kernel() {
    int warp = (blockIdx.x * blockDim.x + threadIdx.x) >> 5;
    int lane = threadIdx.x & 31;
    if (warp >= N_NODES) return;
    int beg = g_off[warp], end = g_off[warp + 1];
    float ax[4] = {0.f, 0.f, 0.f, 0.f};
    float ah[4] = {0.f, 0.f, 0.f, 0.f};
    for (int e = beg; e < end; e++) {
        uint2 ed = g_edge[e];
        int   s = (int)ed.x;
        float w = __uint_as_float(ed.y);
        const uint2* px = (const uint2*)(g_XHb16 + (size_t)s * 256) + lane;
        const uint2* ph = (const uint2*)(g_XHb16 + (size_t)s * 256 + 128) + lane;
        uint2 xv = __ldg(px);
        uint2 hv = __ldg(ph);
        float2 x01 = __bfloat1622float2(*(const __nv_bfloat162*)&xv.x);
        float2 x23 = __bfloat1622float2(*(const __nv_bfloat162*)&xv.y);
        float2 h01 = __bfloat1622float2(*(const __nv_bfloat162*)&hv.x);
        float2 h23 = __bfloat1622float2(*(const __nv_bfloat162*)&hv.y);
        ax[0] = fmaf(w, x01.x, ax[0]); ax[1] = fmaf(w, x01.y, ax[1]);
        ax[2] = fmaf(w, x23.x, ax[2]); ax[3] = fmaf(w, x23.y, ax[3]);
        ah[0] = fmaf(w, h01.x, ah[0]); ah[1] = fmaf(w, h01.y, ah[1]);
        ah[2] = fmaf(w, h23.x, ah[2]); ah[3] = fmaf(w, h23.y, ah[3]);
    }
    float inv = 1.0f / fmaxf((float)(end - beg), 1.0f);
    size_t ba = (size_t)warp * KTOT;
    *(float4*)(g_A + ba + lane * 4) =
        make_float4(tf32f(ax[0] * inv), tf32f(ax[1] * inv), tf32f(ax[2] * inv), tf32f(ax[3] * inv));
    *(float4*)(g_A + ba + 256 + lane * 4) =
        make_float4(tf32f(ah[0] * inv), tf32f(ah[1] * inv), tf32f(ah[2] * inv), tf32f(ah[3] * inv));
}

// ===================== tf32 warp-MMA GEMM + fused LSTM =====================
// Block 128x128, 256 threads (8 warps 2x4), warp tile 64x32, 2 CTAs/SM.
// K: 16 tiles of 32, double-buffered. SMEM rows: 32 fp32 + 4 pad = 144B.
#define ROW_B    144
#define ATILE_B  (128 * ROW_B)        // 18432
#define STAGE_B  (2 * ATILE_B)        // 36864
#define GEMM_SMEM (2 * STAGE_B)       // 73728
#define DSTRIDE  132

__global__ void __launch_bounds__(256, 2) gemm_lstm_kernel(
    const float* __restrict__ C,
    const float* __restrict__ bx, const float* __restrict__ bh, const float* __restrict__ bg,
    const float* __restrict__ wc,
    float* __restrict__ outH, float* __restrict__ outC)
{
    extern __shared__ char sm[];
    uint32_t smb = smem_to_u32(sm);

    int tid = threadIdx.x;
    int wid = tid >> 5, lid = tid & 31;
    int ntile = blockIdx.x;        // 0..3
    int row0  = blockIdx.y * 128;

    // cp.async mapping: thread -> row = tid>>1, half = tid&1 (16 floats)
    int lrow = tid >> 1;
    int half = tid & 1;
    int arow = row0 + lrow; if (arow >= N_NODES) arow = N_NODES - 1;
    int brow = ntile * 128 + lrow;
    uint32_t dst_off = (uint32_t)lrow * ROW_B + half * 64;

    const float* Ap = g_A + (size_t)arow * KTOT;
    const float* Bp = g_B + (size_t)brow * KTOT;

    int mw = (wid >> 2) * 64;
    int nw = (wid & 3) * 32;
    int qr = lid >> 2;
    int qc = lid & 3;

    float acc[4][4][4];
#pragma unroll
    for (int i = 0; i < 4; i++)
#pragma unroll
        for (int j = 0; j < 4; j++)
#pragma unroll
            for (int q = 0; q < 4; q++) acc[i][j][q] = 0.f;

    // prologue: k-tile 0 -> stage 0
    {
        const float* sa = Ap + half * 16;
        const float* sb = Bp + half * 16;
        uint32_t da = smb + dst_off;
        uint32_t db = smb + ATILE_B + dst_off;
#pragma unroll
        for (int j = 0; j < 4; j++) {
            CP_ASYNC16(da + j * 16, sa + j * 4);
            CP_ASYNC16(db + j * 16, sb + j * 4);
        }
        CP_COMMIT();
    }

    int buf = 0;
    for (int kt = 0; kt < 16; kt++) {
        CP_WAIT(0);
        __syncthreads();
        if (kt < 15) {
            int k1 = (kt + 1) * 32;
            const float* sa = Ap + k1 + half * 16;
            const float* sb = Bp + k1 + half * 16;
            uint32_t sbb = smb + (buf ^ 1) * STAGE_B;
            uint32_t da = sbb + dst_off;
            uint32_t db = sbb + ATILE_B + dst_off;
#pragma unroll
            for (int j = 0; j < 4; j++) {
                CP_ASYNC16(da + j * 16, sa + j * 4);
                CP_ASYNC16(db + j * 16, sb + j * 4);
            }
            CP_COMMIT();
        }

        const char* smA = sm + buf * STAGE_B;
        const char* smB = smA + ATILE_B;

#pragma unroll
        for (int ks = 0; ks < 4; ks++) {
            int kc = ks * 8;
            uint32_t a[4][4], b[4][2];
#pragma unroll
            for (int mi = 0; mi < 4; mi++) {
                const char* base = smA + (mw + mi * 16 + qr) * ROW_B + (kc + qc) * 4;
                a[mi][0] = *(const uint32_t*)(base);
                a[mi][1] = *(const uint32_t*)(base + 8 * ROW_B);
                a[mi][2] = *(const uint32_t*)(base + 16);
                a[mi][3] = *(const uint32_t*)(base + 8 * ROW_B + 16);
            }
#pragma unroll
            for (int ni = 0; ni < 4; ni++) {
                const char* base = smB + (nw + ni * 8 + qr) * ROW_B + (kc + qc) * 4;
                b[ni][0] = *(const uint32_t*)(base);
                b[ni][1] = *(const uint32_t*)(base + 16);
            }
#pragma unroll
            for (int mi = 0; mi < 4; mi++)
#pragma unroll
                for (int ni = 0; ni < 4; ni++)
                    MMA_TF32(acc[mi][ni], a[mi], b[ni]);
        }
        buf ^= 1;
    }
    __syncthreads();

    // epilogue: acc -> smem D[128][132]
    float* sD = (float*)sm;
    {
        int r0 = mw + qr;
        int c0 = nw + qc * 2;
#pragma unroll
        for (int mi = 0; mi < 4; mi++)
#pragma unroll
            for (int ni = 0; ni < 4; ni++) {
                int rr = r0 + mi * 16, cc = c0 + ni * 8;
                sD[rr * DSTRIDE + cc]           = acc[mi][ni][0];
                sD[rr * DSTRIDE + cc + 1]       = acc[mi][ni][1];
                sD[(rr + 8) * DSTRIDE + cc]     = acc[mi][ni][2];
                sD[(rr + 8) * DSTRIDE + cc + 1] = acc[mi][ni][3];
            }
    }
    __syncthreads();

    // fused LSTM: thread -> row = tid>>1, 16 outputs
    {
        int row = tid >> 1;
        int r = row0 + row;
        if (r < N_NODES) {
            int ob = (tid & 1) * 16;
            int o0 = ntile * 32 + ob;
#pragma unroll 4
            for (int j = 0; j < 16; j += 4) {
                float4 cold4 = *(const float4*)&C[(size_t)r * DIM + o0 + j];
                float co[4] = {cold4.x, cold4.y, cold4.z, cold4.w};
                float hnew[4], cnew[4];
#pragma unroll
                for (int q = 0; q < 4; q++) {
                    int o = o0 + j + q;
                    float4 gq = *(float4*)&sD[row * DSTRIDE + (ob + j + q) * 4];
                    float gI = gq.x + bx[0 * DIM + o] + bh[0 * DIM + o] + bg[0 * DIM + o] + wc[0 * DIM + o] * co[q];
                    float gF = gq.y + bx[1 * DIM + o] + bh[1 * DIM + o] + bg[1 * DIM + o] + wc[1 * DIM + o] * co[q];
                    float gT = gq.z + bx[2 * DIM + o] + bh[2 * DIM + o] + bg[2 * DIM + o];
                    float I = 1.f / (1.f + expf(-gI));
                    float F = 1.f / (1.f + expf(-gF));
                    float T = tanhf(gT);
                    float cn = fmaf(F, co[q], I * T);
                    float gO = gq.w + bx[3 * DIM + o] + bh[3 * DIM + o] + bg[3 * DIM + o] + wc[2 * DIM + o] * cn;
                    float O = 1.f / (1.f + expf(-gO));
                    hnew[q] = O * tanhf(cn);
                    cnew[q] = cn;
                }
                *(float4*)&outH[(size_t)r * DIM + o0 + j] = make_float4(hnew[0], hnew[1], hnew[2], hnew[3]);
                *(float4*)&outC[(size_t)r * DIM + o0 + j] = make_float4(cnew[0], cnew[1], cnew[2], cnew[3]);
            }
        }
    }
}

// ===================== launch =====================
extern "C" void kernel_launch(void* const* d_in, const int* in_sizes, int n_in,
                              void* d_out, int out_size) {
    const float* X    = (const float*)d_in[0];
    const int*   ei   = (const int*)  d_in[1];
    const float* ew   = (const float*)d_in[2];
    const float* H    = (const float*)d_in[3];
    const float* C    = (const float*)d_in[4];
    const float* Wx_l = (const float*)d_in[5];
    const float* Wx_r = (const float*)d_in[6];
    const float* bx   = (const float*)d_in[7];
    const float* Wh_l = (const float*)d_in[8];
    const float* Wh_r = (const float*)d_in[9];
    const float* bh   = (const float*)d_in[10];
    const float* wc   = (const float*)d_in[11];
    const float* bg   = (const float*)d_in[12];

    float* outH = (float*)d_out;
    float* outC = outH + (size_t)N_NODES * DIM;

    cudaFuncSetAttribute(gemm_lstm_kernel, cudaFuncAttributeMaxDynamicSharedMemorySize, GEMM_SMEM);

    zero_cnt_kernel<<<(N_NODES + 255) / 256, 256>>>();
    count_kernel<<<(N_EDGES + 255) / 256, 256>>>(ei);
    scan_kernel<<<1, 1024>>>();
    scatter_kernel<<<(N_EDGES + 255) / 256, 256>>>(ei, ew);
    prep_kernel<<<(CONV_N + PACK_N + 255) / 256, 256>>>(X, H, Wx_l, Wx_r, Wh_l, Wh_r);
    aggregate_kernel<<<(N_NODES * 32 + 255) / 256, 256>>>();

    dim3 grid(4, MTILES);
    gemm_lstm_kernel<<<grid, 256, GEMM_SMEM>>>(C, bx, bh, bg, wc, outH, outC);
}

// round 6
// speedup vs baseline: 1.8259x; 1.0194x over previous
#include <cuda_runtime.h>
#include <cuda_bf16.h>
#include <math.h>
#include <stdint.h>

#define N_NODES 20000
#define N_EDGES 640000
#define DIM     128
#define KTOT    512     // A cols: [aggX | X | aggH | H]
#define NCOL    512     // 4 gates * 128 outputs, col = o*4 + g
#define MTILES  157     // ceil(20000/128)

// ===================== helpers =====================
__device__ __forceinline__ uint32_t smem_to_u32(const void* p) {
    uint32_t a;
    asm("{ .reg .u64 t; cvta.to.shared.u64 t, %1; cvt.u32.u64 %0, t; }" : "=r"(a) : "l"(p));
    return a;
}
#define CP_ASYNC16(sm, gp) \
    asm volatile("cp.async.cg.shared.global [%0], [%1], 16;" :: "r"(sm), "l"(gp) : "memory")
#define CP_COMMIT() asm volatile("cp.async.commit_group;" ::: "memory")
#define CP_WAIT(n)  asm volatile("cp.async.wait_group %0;" :: "n"(n) : "memory")

#define F2TF32(u, f) asm volatile("cvt.rna.tf32.f32 %0, %1;" : "=r"(u) : "f"(f))
__device__ __forceinline__ float tf32f(float f) { uint32_t u; F2TF32(u, f); return __uint_as_float(u); }

#define MMA_TF32(d, a, b) \
    asm volatile("mma.sync.aligned.m16n8k8.row.col.f32.tf32.tf32.f32 " \
        "{%0,%1,%2,%3}, {%4,%5,%6,%7}, {%8,%9}, {%0,%1,%2,%3};" \
        : "+f"((d)[0]), "+f"((d)[1]), "+f"((d)[2]), "+f"((d)[3]) \
        : "r"((a)[0]), "r"((a)[1]), "r"((a)[2]), "r"((a)[3]), "r"((b)[0]), "r"((b)[1]))

// ===================== scratch =====================
__device__ int   g_cnt[N_NODES];
__device__ int   g_off[N_NODES + 1];
__device__ int   g_pos[N_NODES];
__device__ uint2 g_edge[N_EDGES];                          // {src, weight bits}
__device__ float g_A[(size_t)N_NODES * KTOT];              // tf32-rounded A matrix
__device__ float g_B[(size_t)NCOL * KTOT];                 // tf32-rounded B^T [n][k]
__device__ __nv_bfloat16 g_XHb16[(size_t)N_NODES * 256];   // bf16 gather copy: 128 X | 128 H

#define COUNT_BLOCKS 2500
#define CONV_N (N_NODES * DIM)
#define PACK_N (NCOL * KTOT)
#define PREP_BLOCKS ((CONV_N + PACK_N + 255) / 256)

// ===================== fused count + prep =====================
__global__ void count_prep_kernel(const int* __restrict__ ei,
                                  const float* __restrict__ X, const float* __restrict__ H,
                                  const float* __restrict__ Wx_l, const float* __restrict__ Wx_r,
                                  const float* __restrict__ Wh_l, const float* __restrict__ Wh_r) {
    int b = blockIdx.x;
    if (b < COUNT_BLOCKS) {
        int e = b * 256 + threadIdx.x;
        if (e < N_EDGES) atomicAdd(&g_cnt[ei[N_EDGES + e]], 1);
    } else {
        int idx = (b - COUNT_BLOCKS) * 256 + threadIdx.x;
        if (idx < CONV_N) {
            int r = idx >> 7, c = idx & 127;
            float xv = X[idx], hv = H[idx];
            size_t b16 = (size_t)r * 256;
            g_XHb16[b16 + c]       = __float2bfloat16(xv);
            g_XHb16[b16 + 128 + c] = __float2bfloat16(hv);
            size_t ba = (size_t)r * KTOT;
            g_A[ba + 128 + c] = tf32f(xv);
            g_A[ba + 384 + c] = tf32f(hv);
        } else {
            int j = idx - CONV_N;
            if (j < PACK_N) {
                int n = j >> 9;
                int k = j & 511;
                int o = n >> 2, g = n & 3;
                int kb = k >> 7, d = k & 127;
                const float* W = (kb == 0) ? Wx_l : (kb == 1) ? Wx_r : (kb == 2) ? Wh_l : Wh_r;
                g_B[j] = tf32f(W[(g * DIM + d) * DIM + o]);
            }
        }
    }
}

// ===================== scan (single block, coarsened) =====================
__global__ void scan_kernel() {
    const int PER = 20;
    int t = threadIdx.x;
    int base = t * PER;
    int loc[PER];
    int sum = 0;
#pragma unroll
    for (int j = 0; j < PER; j++) {
        int i = base + j;
        int v = (i < N_NODES) ? g_cnt[i] : 0;
        loc[j] = sum;
        sum += v;
    }
    int lane = t & 31, warp = t >> 5;
    int x = sum;
#pragma unroll
    for (int o = 1; o < 32; o <<= 1) {
        int y = __shfl_up_sync(0xFFFFFFFFu, x, o);
        if (lane >= o) x += y;
    }
    __shared__ int wsum[32];
    if (lane == 31) wsum[warp] = x;
    __syncthreads();
    if (warp == 0) {
        int w = wsum[lane];
#pragma unroll
        for (int o = 1; o < 32; o <<= 1) {
            int y = __shfl_up_sync(0xFFFFFFFFu, w, o);
            if (lane >= o) w += y;
        }
        wsum[lane] = w;
    }
    __syncthreads();
    int warpbase = (warp > 0) ? wsum[warp - 1] : 0;
    int excl = warpbase + x - sum;
#pragma unroll
    for (int j = 0; j < PER; j++) {
        int i = base + j;
        if (i < N_NODES) {
            int p = excl + loc[j];
            g_off[i] = p;
            g_pos[i] = p;
        }
    }
    if (t == 1023) g_off[N_NODES] = warpbase + x;
}

__global__ void scatter_kernel(const int* __restrict__ ei, const float* __restrict__ ew) {
    int e = blockIdx.x * blockDim.x + threadIdx.x;
    if (e < N_EDGES) {
        int d = ei[N_EDGES + e];
        int p = atomicAdd(&g_pos[d], 1);
        g_edge[p] = make_uint2((uint32_t)ei[e], __float_as_uint(ew[e]));
    }
}

// ===================== aggregation: 1 warp/node, 2x unrolled gather =====================
__global__ void aggregate_kernel() {
    int warp = (blockIdx.x * blockDim.x + threadIdx.x) >> 5;
    int lane = threadIdx.x & 31;
    if (warp >= N_NODES) return;
    int beg = g_off[warp], end = g_off[warp + 1];
    float ax[4] = {0.f, 0.f, 0.f, 0.f};
    float ah[4] = {0.f, 0.f, 0.f, 0.f};
    int e = beg;
    for (; e + 1 < end; e += 2) {
        uint2 ed0 = __ldg(&g_edge[e]);
        uint2 ed1 = __ldg(&g_edge[e + 1]);
        int   s0 = (int)ed0.x, s1 = (int)ed1.x;
        float w0 = __uint_as_float(ed0.y), w1 = __uint_as_float(ed1.y);
        uint2 xv0 = __ldg((const uint2*)(g_XHb16 + (size_t)s0 * 256) + lane);
        uint2 hv0 = __ldg((const uint2*)(g_XHb16 + (size_t)s0 * 256 + 128) + lane);
        uint2 xv1 = __ldg((const uint2*)(g_XHb16 + (size_t)s1 * 256) + lane);
        uint2 hv1 = __ldg((const uint2*)(g_XHb16 + (size_t)s1 * 256 + 128) + lane);
        float2 p;
        p = __bfloat1622float2(*(const __nv_bfloat162*)&xv0.x); ax[0] = fmaf(w0, p.x, ax[0]); ax[1] = fmaf(w0, p.y, ax[1]);
        p = __bfloat1622float2(*(const __nv_bfloat162*)&xv0.y); ax[2] = fmaf(w0, p.x, ax[2]); ax[3] = fmaf(w0, p.y, ax[3]);
        p = __bfloat1622float2(*(const __nv_bfloat162*)&hv0.x); ah[0] = fmaf(w0, p.x, ah[0]); ah[1] = fmaf(w0, p.y, ah[1]);
        p = __bfloat1622float2(*(const __nv_bfloat162*)&hv0.y); ah[2] = fmaf(w0, p.x, ah[2]); ah[3] = fmaf(w0, p.y, ah[3]);
        p = __bfloat1622float2(*(const __nv_bfloat162*)&xv1.x); ax[0] = fmaf(w1, p.x, ax[0]); ax[1] = fmaf(w1, p.y, ax[1]);
        p = __bfloat1622float2(*(const __nv_bfloat162*)&xv1.y); ax[2] = fmaf(w1, p.x, ax[2]); ax[3] = fmaf(w1, p.y, ax[3]);
        p = __bfloat1622float2(*(const __nv_bfloat162*)&hv1.x); ah[0] = fmaf(w1, p.x, ah[0]); ah[1] = fmaf(w1, p.y, ah[1]);
        p = __bfloat1622float2(*(const __nv_bfloat162*)&hv1.y); ah[2] = fmaf(w1, p.x, ah[2]); ah[3] = fmaf(w1, p.y, ah[3]);
    }
    if (e < end) {
        uint2 ed = __ldg(&g_edge[e]);
        int   s = (int)ed.x;
        float w = __uint_as_float(ed.y);
        uint2 xv = __ldg((const uint2*)(g_XHb16 + (size_t)s * 256) + lane);
        uint2 hv = __ldg((const uint2*)(g_XHb16 + (size_t)s * 256 + 128) + lane);
        float2 p;
        p = __bfloat1622float2(*(const __nv_bfloat162*)&xv.x); ax[0] = fmaf(w, p.x, ax[0]); ax[1] = fmaf(w, p.y, ax[1]);
        p = __bfloat1622float2(*(const __nv_bfloat162*)&xv.y); ax[2] = fmaf(w, p.x, ax[2]); ax[3] = fmaf(w, p.y, ax[3]);
        p = __bfloat1622float2(*(const __nv_bfloat162*)&hv.x); ah[0] = fmaf(w, p.x, ah[0]); ah[1] = fmaf(w, p.y, ah[1]);
        p = __bfloat1622float2(*(const __nv_bfloat162*)&hv.y); ah[2] = fmaf(w, p.x, ah[2]); ah[3] = fmaf(w, p.y, ah[3]);
    }
    float inv = 1.0f / fmaxf((float)(end - beg), 1.0f);
    size_t ba = (size_t)warp * KTOT;
    *(float4*)(g_A + ba + lane * 4) =
        make_float4(tf32f(ax[0] * inv), tf32f(ax[1] * inv), tf32f(ax[2] * inv), tf32f(ax[3] * inv));
    *(float4*)(g_A + ba + 256 + lane * 4) =
        make_float4(tf32f(ah[0] * inv), tf32f(ah[1] * inv), tf32f(ah[2] * inv), tf32f(ah[3] * inv));
}

// ===================== tf32 warp-MMA GEMM + fused LSTM =====================
// Block 128x128, 256 threads (8 warps 2x4), warp tile 64x32, 2 CTAs/SM.
// K: 16 tiles of 32, double-buffered. SMEM rows: 32 fp32 + 4 pad = 144B.
#define ROW_B    144
#define ATILE_B  (128 * ROW_B)        // 18432
#define STAGE_B  (2 * ATILE_B)        // 36864
#define GEMM_SMEM (2 * STAGE_B)       // 73728
#define DSTRIDE  132

__global__ void __launch_bounds__(256, 2) gemm_lstm_kernel(
    const float* __restrict__ C,
    const float* __restrict__ bx, const float* __restrict__ bh, const float* __restrict__ bg,
    const float* __restrict__ wc,
    float* __restrict__ outH, float* __restrict__ outC)
{
    extern __shared__ char sm[];
    uint32_t smb = smem_to_u32(sm);

    int tid = threadIdx.x;
    int wid = tid >> 5, lid = tid & 31;
    int ntile = blockIdx.x;        // 0..3
    int row0  = blockIdx.y * 128;

    // cp.async mapping: thread -> row = tid>>1, half = tid&1 (16 floats)
    int lrow = tid >> 1;
    int half = tid & 1;
    int arow = row0 + lrow; if (arow >= N_NODES) arow = N_NODES - 1;
    int brow = ntile * 128 + lrow;
    uint32_t dst_off = (uint32_t)lrow * ROW_B + half * 64;

    const float* Ap = g_A + (size_t)arow * KTOT + half * 16;
    const float* Bp = g_B + (size_t)brow * KTOT + half * 16;

    int mw = (wid >> 2) * 64;
    int nw = (wid & 3) * 32;
    int qr = lid >> 2;
    int qc = lid & 3;

    // precomputed smem offsets (within a stage)
    uint32_t offA = (uint32_t)(mw + qr) * ROW_B + qc * 4;           // + mi*16*ROW_B + kc*4
    uint32_t offB = (uint32_t)ATILE_B + (uint32_t)(nw + qr) * ROW_B + qc * 4;

    float acc[4][4][4];
#pragma unroll
    for (int i = 0; i < 4; i++)
#pragma unroll
        for (int j = 0; j < 4; j++)
#pragma unroll
            for (int q = 0; q < 4; q++) acc[i][j][q] = 0.f;

    // prologue: k-tile 0 -> stage 0
    {
        uint32_t da = smb + dst_off;
        uint32_t db = smb + ATILE_B + dst_off;
#pragma unroll
        for (int j = 0; j < 4; j++) {
            CP_ASYNC16(da + j * 16, Ap + j * 4);
            CP_ASYNC16(db + j * 16, Bp + j * 4);
        }
        CP_COMMIT();
    }

    int buf = 0;
    for (int kt = 0; kt < 16; kt++) {
        CP_WAIT(0);
        __syncthreads();
        if (kt < 15) {
            int k1 = (kt + 1) * 32;
            uint32_t sbb = smb + (buf ^ 1) * STAGE_B;
            uint32_t da = sbb + dst_off;
            uint32_t db = sbb + ATILE_B + dst_off;
#pragma unroll
            for (int j = 0; j < 4; j++) {
                CP_ASYNC16(da + j * 16, Ap + k1 + j * 4);
                CP_ASYNC16(db + j * 16, Bp + k1 + j * 4);
            }
            CP_COMMIT();
        }

        const char* stage = sm + buf * STAGE_B;

#pragma unroll
        for (int ks = 0; ks < 4; ks++) {
            uint32_t kb = ks * 32;   // kc*4 bytes
            uint32_t b[4][2];
#pragma unroll
            for (int ni = 0; ni < 4; ni++) {
                const char* pb = stage + offB + ni * (8 * ROW_B) + kb;
                b[ni][0] = *(const uint32_t*)(pb);
                b[ni][1] = *(const uint32_t*)(pb + 16);
            }
#pragma unroll
            for (int mi = 0; mi < 4; mi++) {
                const char* pa = stage + offA + mi * (16 * ROW_B) + kb;
                uint32_t a[4];
                a[0] = *(const uint32_t*)(pa);
                a[1] = *(const uint32_t*)(pa + 8 * ROW_B);
                a[2] = *(const uint32_t*)(pa + 16);
                a[3] = *(const uint32_t*)(pa + 8 * ROW_B + 16);
#pragma unroll
                for (int ni = 0; ni < 4; ni++)
                    MMA_TF32(acc[mi][ni], a, b[ni]);
            }
        }
        buf ^= 1;
    }
    __syncthreads();

    // epilogue: acc -> smem D[128][132]
    float* sD = (float*)sm;
    {
        int r0 = mw + qr;
        int c0 = nw + qc * 2;
#pragma unroll
        for (int mi = 0; mi < 4; mi++)
#pragma unroll
            for (int ni = 0; ni < 4; ni++) {
                int rr = r0 + mi * 16, cc = c0 + ni * 8;
                sD[rr * DSTRIDE + cc]           = acc[mi][ni][0];
                sD[rr * DSTRIDE + cc + 1]       = acc[mi][ni][1];
                sD[(rr + 8) * DSTRIDE + cc]     = acc[mi][ni][2];
                sD[(rr + 8) * DSTRIDE + cc + 1] = acc[mi][ni][3];
            }
    }
    __syncthreads();

    // fused LSTM: thread -> row = tid>>1, 16 outputs
    {
        int row = tid >> 1;
        int r = row0 + row;
        if (r < N_NODES) {
            int ob = (tid & 1) * 16;
            int o0 = ntile * 32 + ob;
#pragma unroll 4
            for (int j = 0; j < 16; j += 4) {
                float4 cold4 = *(const float4*)&C[(size_t)r * DIM + o0 + j];
                float co[4] = {cold4.x, cold4.y, cold4.z, cold4.w};
                float hnew[4], cnew[4];
#pragma unroll
                for (int q = 0; q < 4; q++) {
                    int o = o0 + j + q;
                    float4 gq = *(float4*)&sD[row * DSTRIDE + (ob + j + q) * 4];
                    float gI = gq.x + bx[0 * DIM + o] + bh[0 * DIM + o] + bg[0 * DIM + o] + wc[0 * DIM + o] * co[q];
                    float gF = gq.y + bx[1 * DIM + o] + bh[1 * DIM + o] + bg[1 * DIM + o] + wc[1 * DIM + o] * co[q];
                    float gT = gq.z + bx[2 * DIM + o] + bh[2 * DIM + o] + bg[2 * DIM + o];
                    float I = 1.f / (1.f + expf(-gI));
                    float F = 1.f / (1.f + expf(-gF));
                    float T = tanhf(gT);
                    float cn = fmaf(F, co[q], I * T);
                    float gO = gq.w + bx[3 * DIM + o] + bh[3 * DIM + o] + bg[3 * DIM + o] + wc[2 * DIM + o] * cn;
                    float O = 1.f / (1.f + expf(-gO));
                    hnew[q] = O * tanhf(cn);
                    cnew[q] = cn;
                }
                *(float4*)&outH[(size_t)r * DIM + o0 + j] = make_float4(hnew[0], hnew[1], hnew[2], hnew[3]);
                *(float4*)&outC[(size_t)r * DIM + o0 + j] = make_float4(cnew[0], cnew[1], cnew[2], cnew[3]);
            }
        }
    }
}

// ===================== launch =====================
extern "C" void kernel_launch(void* const* d_in, const int* in_sizes, int n_in,
                              void* d_out, int out_size) {
    const float* X    = (const float*)d_in[0];
    const int*   ei   = (const int*)  d_in[1];
    const float* ew   = (const float*)d_in[2];
    const float* H    = (const float*)d_in[3];
    const float* C    = (const float*)d_in[4];
    const float* Wx_l = (const float*)d_in[5];
    const float* Wx_r = (const float*)d_in[6];
    const float* bx   = (const float*)d_in[7];
    const float* Wh_l = (const float*)d_in[8];
    const float* Wh_r = (const float*)d_in[9];
    const float* bh   = (const float*)d_in[10];
    const float* wc   = (const float*)d_in[11];
    const float* bg   = (const float*)d_in[12];

    float* outH = (float*)d_out;
    float* outC = outH + (size_t)N_NODES * DIM;

    cudaFuncSetAttribute(gemm_lstm_kernel, cudaFuncAttributeMaxDynamicSharedMemorySize, GEMM_SMEM);

    void* cnt_ptr = nullptr;
    cudaGetSymbolAddress(&cnt_ptr, g_cnt);
    cudaMemsetAsync(cnt_ptr, 0, sizeof(int) * N_NODES);

    count_prep_kernel<<<COUNT_BLOCKS + PREP_BLOCKS, 256>>>(ei, X, H, Wx_l, Wx_r, Wh_l, Wh_r);
    scan_kernel<<<1, 1024>>>();
    scatter_kernel<<<(N_EDGES + 255) / 256, 256>>>(ei, ew);
    aggregate_kernel<<<(N_NODES * 32 + 255) / 256, 256>>>();

    dim3 grid(4, MTILES);
    gemm_lstm_kernel<<<grid, 256, GEMM_SMEM>>>(C, bx, bh, bg, wc, outH, outC);
}